// round 9
// baseline (speedup 1.0000x reference)
#include <cuda_runtime.h>
#include <cuda_bf16.h>

// ===========================================================================
// EuclideanCodebook: ind = argmax_c ( x·e_c - 0.5||e_c||^2 ), q = embed[ind].
// R9: 2-term bf16 split GEMM on mma.sync.m16n8k16 (R6's proven structure):
//   x = xh + xl (bf16 split, ~exact), e ~= eh (bf16)
//   x·e ~= xh·eh + xl·eh ; error std ~= 1.1e-3 * ||x||
// Rows with top2-margin < 0.014*||x|| (~9 sigma) exactly re-scored in fp32.
// ===========================================================================

#define NROWS   131072
#define KCODES  1024
#define STRIDE_A 528            // A row: 512B payload [xh|xl] + 16B pad
#define STRIDE_B 272            // B row: 256B payload [eh] + 16B pad

// smem byte offsets
#define S_HN    0                         // 1024 floats
#define S_XN    4096                      // 128 floats (row ||x||^2)
#define S_A     4608                      // 128 x 528
#define S_B0    (S_A  + 67584)            // 72192 ; 128 x 272
#define S_B1    (S_B0 + 34816)            // 107008
#define S_BV    (S_B1 + 34816)            // 141824 ; float[4][128]
#define S_V2    (S_BV + 2048)
#define S_BI    (S_V2 + 2048)
#define S_IND   (S_BI + 2048)
#define S_TOTAL (S_IND + 512)             // 148480 B

// __device__ scratch (allocation-free)
__device__ __align__(16) __nv_bfloat16 g_Eh[KCODES * 128];
__device__ float g_hn[KCODES];
__device__ int   g_rcnt;
__device__ int   g_rrows[NROWS];

// ---------------------------------------------------------------------------
__device__ __forceinline__ unsigned smem_u32(const void* p) {
    unsigned a;
    asm("{ .reg .u64 t; cvta.to.shared.u64 t, %1; cvt.u32.u64 %0, t; }"
        : "=r"(a) : "l"(p));
    return a;
}

#define LDSM_X4(r, addr)                                                      \
    asm volatile("ldmatrix.sync.aligned.m8n8.x4.shared.b16 {%0,%1,%2,%3}, [%4];" \
        : "=r"((r)[0]), "=r"((r)[1]), "=r"((r)[2]), "=r"((r)[3]) : "r"(addr))

#define MMA16816(d, a, b0, b1)                                                \
    asm volatile("mma.sync.aligned.m16n8k16.row.col.f32.bf16.bf16.f32 "       \
        "{%0,%1,%2,%3}, {%4,%5,%6,%7}, {%8,%9}, {%0,%1,%2,%3};"               \
        : "+f"((d)[0]), "+f"((d)[1]), "+f"((d)[2]), "+f"((d)[3])              \
        : "r"((a)[0]), "r"((a)[1]), "r"((a)[2]), "r"((a)[3]), "r"(b0), "r"(b1))

#define CP_COMMIT() asm volatile("cp.async.commit_group;" ::: "memory")
#define CP_WAIT1()  asm volatile("cp.async.wait_group 1;" ::: "memory")

__device__ __forceinline__ unsigned pack_bf16x2(float a, float b) {
    __nv_bfloat162 h = __floats2bfloat162_rn(a, b);
    return *(unsigned*)&h;
}

// ---------------------------------------------------------------------------
// prep_e: warp per code. Converts to bf16 (eh only), computes 0.5||e||^2.
// ---------------------------------------------------------------------------
__global__ void prep_e(const float* __restrict__ embed) {
    int w = (blockIdx.x * blockDim.x + threadIdx.x) >> 5;   // code
    int lane = threadIdx.x & 31;
    if (w == 0 && lane == 0) g_rcnt = 0;
    if (w >= KCODES) return;
    float4 v = ((const float4*)(embed + (size_t)w * 128))[lane];
    float s = v.x * v.x + v.y * v.y + v.z * v.z + v.w * v.w;
#pragma unroll
    for (int off = 16; off > 0; off >>= 1)
        s += __shfl_xor_sync(0xffffffffu, s, off);
    if (lane == 0) g_hn[w] = 0.5f * s;
    uint2 o;
    o.x = pack_bf16x2(v.x, v.y);
    o.y = pack_bf16x2(v.z, v.w);
    ((uint2*)(g_Eh + (size_t)w * 128))[lane] = o;
}

// ---------------------------------------------------------------------------
// B chunk loader: 128 codes x 128 bf16 (256 B/code) -> smem [code][272]
// ---------------------------------------------------------------------------
__device__ __forceinline__ void load_B_async(unsigned sb, int ch, int bufOff, int tid) {
    const char* src = (const char*)(g_Eh + (size_t)ch * 128 * 128);
#pragma unroll
    for (int it = 0; it < 8; it++) {
        int idx = tid + it * 256;
        int r = idx >> 4, kk = idx & 15;
        unsigned dst = sb + bufOff + r * STRIDE_B + kk * 16;
        asm volatile("cp.async.cg.shared.global [%0], [%1], 16;"
                     :: "r"(dst), "l"(src + r * 256 + kk * 16));
    }
}

// ---------------------------------------------------------------------------
// main: 1024 CTAs x 256 threads; CTA = 128 rows x 1024 codes (8 chunks x 128).
// Warps 2(row) x 4(code); warp tile 64 x 32. Two split-terms share B frags.
// ---------------------------------------------------------------------------
__global__ __launch_bounds__(256, 1)
void vq_main(const float* __restrict__ x, const float* __restrict__ embed,
             float* __restrict__ out_ind, float* __restrict__ out_q) {
    extern __shared__ char smem[];
    unsigned sb = smem_u32(smem);
    const int tid  = threadIdx.x;
    const int lane = tid & 31, wid = tid >> 5;
    const int wr = wid & 1, wc = wid >> 1;
    const int rowBase = blockIdx.x * 128;
    float* hnS = (float*)(smem + S_HN);
    float* xnS = (float*)(smem + S_XN);

    // ---- prologue: hn + fused x->bf16-split A tile (+ row norms) ----
    ((float4*)hnS)[tid] = ((const float4*)g_hn)[tid];
    {
        const float4* src = (const float4*)(x + (size_t)rowBase * 128);
#pragma unroll
        for (int it = 0; it < 16; it++) {
            int idx = tid + it * 256;
            int r = idx >> 5, kk = idx & 31;    // one warp covers one row
            float4 v = src[idx];
            float loc = v.x * v.x + v.y * v.y + v.z * v.z + v.w * v.w;
            __nv_bfloat16 h0 = __float2bfloat16(v.x), h1 = __float2bfloat16(v.y);
            __nv_bfloat16 h2 = __float2bfloat16(v.z), h3 = __float2bfloat16(v.w);
            uint2 hi, lo;
            { __nv_bfloat162 t0(h0, h1), t1(h2, h3);
              hi.x = *(unsigned*)&t0; hi.y = *(unsigned*)&t1; }
            lo.x = pack_bf16x2(v.x - __bfloat162float(h0), v.y - __bfloat162float(h1));
            lo.y = pack_bf16x2(v.z - __bfloat162float(h2), v.w - __bfloat162float(h3));
            *(uint2*)(smem + S_A + r * STRIDE_A + kk * 8)       = hi;
            *(uint2*)(smem + S_A + r * STRIDE_A + 256 + kk * 8) = lo;
#pragma unroll
            for (int off = 16; off > 0; off >>= 1)
                loc += __shfl_xor_sync(0xffffffffu, loc, off);
            if (kk == 0) xnS[r] = loc;
        }
    }
    load_B_async(sb, 0, S_B0, tid); CP_COMMIT();
    load_B_async(sb, 1, S_B1, tid); CP_COMMIT();

    float bv[8], v2[8]; int bi[8];
#pragma unroll
    for (int s = 0; s < 8; s++) { bv[s] = -3.4e38f; v2[s] = -3.4e38f; bi[s] = 0; }

    const unsigned aRowOff = (unsigned)(wr * 64 + (lane & 15)) * STRIDE_A
                             + ((lane >> 4) * 16);
    const unsigned bRowOff = (unsigned)(wc * 32 + ((lane >> 4) * 8) + (lane & 7)) * STRIDE_B
                             + (((lane >> 3) & 1) * 16);

    for (int ch = 0; ch < 8; ch++) {
        CP_WAIT1();
        __syncthreads();                       // chunk ch resident

        float d[4][4][4];
#pragma unroll
        for (int mt = 0; mt < 4; mt++)
#pragma unroll
            for (int nt = 0; nt < 4; nt++)
#pragma unroll
                for (int e = 0; e < 4; e++) d[mt][nt][e] = 0.f;

        const unsigned Abase = sb + S_A + aRowOff;
        const unsigned Bbase = sb + ((ch & 1) ? S_B1 : S_B0) + bRowOff;

#pragma unroll
        for (int kk = 0; kk < 8; kk++) {
            unsigned ah[4][4], al[4][4];
#pragma unroll
            for (int mt = 0; mt < 4; mt++) {
                LDSM_X4(ah[mt], Abase + mt * (16 * STRIDE_A) + kk * 32);
                LDSM_X4(al[mt], Abase + mt * (16 * STRIDE_A) + 256 + kk * 32);
            }
            unsigned bh[2][4];
#pragma unroll
            for (int j = 0; j < 2; j++)
                LDSM_X4(bh[j], Bbase + j * (16 * STRIDE_B) + kk * 32);
#pragma unroll
            for (int mt = 0; mt < 4; mt++)
#pragma unroll
                for (int nt = 0; nt < 4; nt++) {
                    unsigned b0 = bh[nt >> 1][(nt & 1) * 2];
                    unsigned b1 = bh[nt >> 1][(nt & 1) * 2 + 1];
                    MMA16816(d[mt][nt], ah[mt], b0, b1);   // xh·eh
                    MMA16816(d[mt][nt], al[mt], b0, b1);   // xl·eh
                }
        }

        // ---- fold -0.5||e||^2, running top-2 ----
        const int cb = ch * 128 + wc * 32 + (lane & 3) * 2;
#pragma unroll
        for (int mt = 0; mt < 4; mt++)
#pragma unroll
            for (int h = 0; h < 2; h++) {
                const int s = mt * 2 + h;
#pragma unroll
                for (int nt = 0; nt < 4; nt++)
#pragma unroll
                    for (int e = 0; e < 2; e++) {
                        int code = cb + nt * 8 + e;
                        float v = d[mt][nt][h * 2 + e] - hnS[code];
                        if (v > bv[s]) { v2[s] = bv[s]; bv[s] = v; bi[s] = code; }
                        else if (v > v2[s]) v2[s] = v;
                    }
            }

        __syncthreads();
        if (ch + 2 < 8) { load_B_async(sb, ch + 2, (ch & 1) ? S_B1 : S_B0, tid); CP_COMMIT(); }
    }

    // ---- reduce across 4 lanes sharing each row ----
#pragma unroll
    for (int s = 0; s < 8; s++) {
#pragma unroll
        for (int off = 1; off <= 2; off <<= 1) {
            float ov = __shfl_xor_sync(0xffffffffu, bv[s], off);
            float o2 = __shfl_xor_sync(0xffffffffu, v2[s], off);
            int   oi = __shfl_xor_sync(0xffffffffu, bi[s], off);
            float mn = fminf(bv[s], ov);
            v2[s] = fmaxf(fmaxf(v2[s], o2), mn);
            if (ov > bv[s] || (ov == bv[s] && oi < bi[s])) { bv[s] = ov; bi[s] = oi; }
        }
    }
    if ((lane & 3) == 0) {
#pragma unroll
        for (int s = 0; s < 8; s++) {
            int mt = s >> 1, h = s & 1;
            int r = wr * 64 + mt * 16 + h * 8 + (lane >> 2);
            ((float*)(smem + S_BV))[wc * 128 + r] = bv[s];
            ((float*)(smem + S_V2))[wc * 128 + r] = v2[s];
            ((int*)(smem + S_BI))[wc * 128 + r]   = bi[s];
        }
    }
    __syncthreads();

    // ---- merge strips, write ind, flag small margins (row-adaptive) ----
    if (tid < 128) {
        float B = -3.4e38f, S2 = -3.4e38f; int I = 0;
#pragma unroll
        for (int w = 0; w < 4; w++) {
            float ov = ((const float*)(smem + S_BV))[w * 128 + tid];
            float o2 = ((const float*)(smem + S_V2))[w * 128 + tid];
            int   oi = ((const int*)(smem + S_BI))[w * 128 + tid];
            float mn = fminf(B, ov);
            S2 = fmaxf(fmaxf(S2, o2), mn);
            if (ov > B || (ov == B && oi < I)) { B = ov; I = oi; }
        }
        int row = rowBase + tid;
        if (out_ind) out_ind[row] = (float)I;
        float eps = 0.014f * sqrtf(xnS[tid]);
        if (B - S2 < eps) {
            int s = atomicAdd(&g_rcnt, 1);
            if (s < NROWS) g_rrows[s] = row;
        }
        ((int*)(smem + S_IND))[tid] = I;
    }
    __syncthreads();

    // ---- cooperative gather of quantize rows ----
    if (out_q) {
        const int* inds = (const int*)(smem + S_IND);
        for (int i = tid; i < 128 * 32; i += 256) {
            int r = i >> 5, c4 = i & 31;
            float4 v = ((const float4*)(embed + (size_t)inds[r] * 128))[c4];
            ((float4*)(out_q + (size_t)(rowBase + r) * 128))[c4] = v;
        }
    }
}

// ---------------------------------------------------------------------------
// rescue: exact fp32 re-score. Block per flagged row, 256 thr, 4 codes each.
// ---------------------------------------------------------------------------
__global__ __launch_bounds__(256, 4)
void rescue_kernel(const float* __restrict__ x,
                   const float* __restrict__ embed,
                   float* __restrict__ out_ind,
                   float* __restrict__ out_q) {
    __shared__ float4 xs4[32];
    __shared__ float bvs[256];
    __shared__ int   bis[256];
    const int tid = threadIdx.x;
    const int cnt = g_rcnt < NROWS ? g_rcnt : NROWS;

    for (int it = blockIdx.x; it < cnt; it += gridDim.x) {
        int row = g_rrows[it];
        if (tid < 32) xs4[tid] = ((const float4*)(x + (size_t)row * 128))[tid];
        __syncthreads();

        float bv = -3.4e38f;
        int   bi = 0;
#pragma unroll
        for (int j = 0; j < 4; j++) {
            int c = j * 256 + tid;
            const float4* e4 = (const float4*)(embed + (size_t)c * 128);
            float s0 = 0.f, s1 = 0.f, s2 = 0.f, s3 = 0.f;
#pragma unroll
            for (int i = 0; i < 8; i++) {
                float4 xa = xs4[i * 4 + 0], ea = e4[i * 4 + 0];
                float4 xb = xs4[i * 4 + 1], eb = e4[i * 4 + 1];
                float4 xc = xs4[i * 4 + 2], ec = e4[i * 4 + 2];
                float4 xd = xs4[i * 4 + 3], ed = e4[i * 4 + 3];
                s0 = fmaf(xa.x, ea.x, fmaf(xa.y, ea.y, fmaf(xa.z, ea.z, fmaf(xa.w, ea.w, s0))));
                s1 = fmaf(xb.x, eb.x, fmaf(xb.y, eb.y, fmaf(xb.z, eb.z, fmaf(xb.w, eb.w, s1))));
                s2 = fmaf(xc.x, ec.x, fmaf(xc.y, ec.y, fmaf(xc.z, ec.z, fmaf(xc.w, ec.w, s2))));
                s3 = fmaf(xd.x, ed.x, fmaf(xd.y, ed.y, fmaf(xd.z, ed.z, fmaf(xd.w, ed.w, s3))));
            }
            float s = (s0 + s1) + (s2 + s3) - g_hn[c];
            if (s > bv) { bv = s; bi = c; }
        }
        bvs[tid] = bv; bis[tid] = bi;
        __syncthreads();
#pragma unroll
        for (int st = 128; st > 0; st >>= 1) {
            if (tid < st) {
                float ov = bvs[tid + st]; int oi = bis[tid + st];
                if (ov > bvs[tid] || (ov == bvs[tid] && oi < bis[tid])) {
                    bvs[tid] = ov; bis[tid] = oi;
                }
            }
            __syncthreads();
        }
        int fi = bis[0];
        if (tid == 0 && out_ind) out_ind[row] = (float)fi;
        if (out_q && tid < 32)
            ((float4*)(out_q + (size_t)row * 128))[tid] =
                ((const float4*)(embed + (size_t)fi * 128))[tid];
        __syncthreads();
    }
}

// ---------------------------------------------------------------------------
extern "C" void kernel_launch(void* const* d_in, const int* in_sizes, int n_in,
                              void* d_out, int out_size) {
    const float* x     = (const float*)d_in[0];
    const float* embed = (const float*)d_in[1];
    const int N = in_sizes[0] / 128;   // 131072

    float* out     = (float*)d_out;
    float* out_ind = out;              // layout: [ind (N)][quantize (N*128)]
    float* out_q   = out + N;
    long long os = (long long)out_size;
    if (os == (long long)N * 128) { out_ind = nullptr; out_q = out; }
    else if (os == (long long)N)  { out_q = nullptr; }

    prep_e<<<KCODES / 8, 256>>>(embed);

    cudaFuncSetAttribute(vq_main, cudaFuncAttributeMaxDynamicSharedMemorySize,
                         S_TOTAL);
    vq_main<<<N / 128, 256, S_TOTAL>>>(x, embed, out_ind, out_q);

    rescue_kernel<<<4096, 256>>>(x, embed, out_ind, out_q);
}

// round 10
// speedup vs baseline: 2.2280x; 2.2280x over previous
#include <cuda_runtime.h>
#include <cuda_bf16.h>

// ===========================================================================
// EuclideanCodebook: ind = argmax_c ( x·e_c - 0.5||e_c||^2 ), q = embed[ind].
// R10: 2-term bf16 split GEMM (R6 loop shape): x = xh + xl, e ~= eh.
//   x·e ~= xh·eh + xl·eh ; score error std ~0.0125 (for ||x||~11.3)
// Rows with top2-margin < 0.012*||x|| re-scored exactly by a BATCHED rescue
// (16 rows/block, embed chunks staged in smem -> 32KB L2 traffic per row).
// ===========================================================================

#define NROWS   131072
#define KCODES  1024
#define STRIDE_A 528            // A row: 512B payload [xh|xl] + 16B pad
#define STRIDE_B 272            // B row: 256B payload [eh] + 16B pad

// smem byte offsets (main kernel)
#define S_HN    0                         // 1024 floats
#define S_XN    4096                      // 128 floats (row ||x||^2)
#define S_A     4608                      // 128 x 528
#define S_B0    (S_A  + 67584)            // 128 x 272
#define S_B1    (S_B0 + 34816)
#define S_BV    (S_B1 + 34816)            // float[4][128]
#define S_V2    (S_BV + 2048)
#define S_BI    (S_V2 + 2048)
#define S_IND   (S_BI + 2048)
#define S_TOTAL (S_IND + 512)             // 148480 B

// __device__ scratch (allocation-free)
__device__ __align__(16) __nv_bfloat16 g_Eh[KCODES * 128];
__device__ float g_hn[KCODES];
__device__ int   g_rcnt;
__device__ int   g_rrows[NROWS];

// ---------------------------------------------------------------------------
__device__ __forceinline__ unsigned smem_u32(const void* p) {
    unsigned a;
    asm("{ .reg .u64 t; cvta.to.shared.u64 t, %1; cvt.u32.u64 %0, t; }"
        : "=r"(a) : "l"(p));
    return a;
}

#define LDSM_X4(r, addr)                                                      \
    asm volatile("ldmatrix.sync.aligned.m8n8.x4.shared.b16 {%0,%1,%2,%3}, [%4];" \
        : "=r"((r)[0]), "=r"((r)[1]), "=r"((r)[2]), "=r"((r)[3]) : "r"(addr))

#define MMA16816(d, a, b0, b1)                                                \
    asm volatile("mma.sync.aligned.m16n8k16.row.col.f32.bf16.bf16.f32 "       \
        "{%0,%1,%2,%3}, {%4,%5,%6,%7}, {%8,%9}, {%0,%1,%2,%3};"               \
        : "+f"((d)[0]), "+f"((d)[1]), "+f"((d)[2]), "+f"((d)[3])              \
        : "r"((a)[0]), "r"((a)[1]), "r"((a)[2]), "r"((a)[3]), "r"(b0), "r"(b1))

#define CP_COMMIT() asm volatile("cp.async.commit_group;" ::: "memory")
#define CP_WAIT1()  asm volatile("cp.async.wait_group 1;" ::: "memory")

__device__ __forceinline__ unsigned pack_bf16x2(float a, float b) {
    __nv_bfloat162 h = __floats2bfloat162_rn(a, b);
    return *(unsigned*)&h;
}

// ---------------------------------------------------------------------------
// prep_e: warp per code. bf16 convert + 0.5||e||^2.
// ---------------------------------------------------------------------------
__global__ void prep_e(const float* __restrict__ embed) {
    int w = (blockIdx.x * blockDim.x + threadIdx.x) >> 5;   // code
    int lane = threadIdx.x & 31;
    if (w == 0 && lane == 0) g_rcnt = 0;
    if (w >= KCODES) return;
    float4 v = ((const float4*)(embed + (size_t)w * 128))[lane];
    float s = v.x * v.x + v.y * v.y + v.z * v.z + v.w * v.w;
#pragma unroll
    for (int off = 16; off > 0; off >>= 1)
        s += __shfl_xor_sync(0xffffffffu, s, off);
    if (lane == 0) g_hn[w] = 0.5f * s;
    uint2 o;
    o.x = pack_bf16x2(v.x, v.y);
    o.y = pack_bf16x2(v.z, v.w);
    ((uint2*)(g_Eh + (size_t)w * 128))[lane] = o;
}

// ---------------------------------------------------------------------------
__device__ __forceinline__ void load_B_async(unsigned sb, int ch, int bufOff, int tid) {
    const char* src = (const char*)(g_Eh + (size_t)ch * 128 * 128);
#pragma unroll
    for (int it = 0; it < 8; it++) {
        int idx = tid + it * 256;
        int r = idx >> 4, kk = idx & 15;
        unsigned dst = sb + bufOff + r * STRIDE_B + kk * 16;
        asm volatile("cp.async.cg.shared.global [%0], [%1], 16;"
                     :: "r"(dst), "l"(src + r * 256 + kk * 16));
    }
}

// ---------------------------------------------------------------------------
// main: 1024 CTAs x 256 threads; CTA = 128 rows x 1024 codes (8 chunks x 128).
// Warps 2(row) x 4(code); warp tile 64 x 32. Two split-terms share B frags.
// ---------------------------------------------------------------------------
__global__ __launch_bounds__(256, 1)
void vq_main(const float* __restrict__ x, const float* __restrict__ embed,
             float* __restrict__ out_ind, float* __restrict__ out_q) {
    extern __shared__ char smem[];
    unsigned sb = smem_u32(smem);
    const int tid  = threadIdx.x;
    const int lane = tid & 31, wid = tid >> 5;
    const int wr = wid & 1, wc = wid >> 1;
    const int rowBase = blockIdx.x * 128;
    float* hnS = (float*)(smem + S_HN);
    float* xnS = (float*)(smem + S_XN);

    // ---- prologue: hn + fused x->bf16-split A tile (+ row norms) ----
    ((float4*)hnS)[tid] = ((const float4*)g_hn)[tid];
    {
        const float4* src = (const float4*)(x + (size_t)rowBase * 128);
#pragma unroll
        for (int it = 0; it < 16; it++) {
            int idx = tid + it * 256;
            int r = idx >> 5, kk = idx & 31;    // one warp covers one row
            float4 v = src[idx];
            float loc = v.x * v.x + v.y * v.y + v.z * v.z + v.w * v.w;
            __nv_bfloat16 h0 = __float2bfloat16(v.x), h1 = __float2bfloat16(v.y);
            __nv_bfloat16 h2 = __float2bfloat16(v.z), h3 = __float2bfloat16(v.w);
            uint2 hi, lo;
            { __nv_bfloat162 t0(h0, h1), t1(h2, h3);
              hi.x = *(unsigned*)&t0; hi.y = *(unsigned*)&t1; }
            lo.x = pack_bf16x2(v.x - __bfloat162float(h0), v.y - __bfloat162float(h1));
            lo.y = pack_bf16x2(v.z - __bfloat162float(h2), v.w - __bfloat162float(h3));
            *(uint2*)(smem + S_A + r * STRIDE_A + kk * 8)       = hi;
            *(uint2*)(smem + S_A + r * STRIDE_A + 256 + kk * 8) = lo;
#pragma unroll
            for (int off = 16; off > 0; off >>= 1)
                loc += __shfl_xor_sync(0xffffffffu, loc, off);
            if (kk == 0) xnS[r] = loc;
        }
    }
    load_B_async(sb, 0, S_B0, tid); CP_COMMIT();
    load_B_async(sb, 1, S_B1, tid); CP_COMMIT();

    float bv[8], v2[8]; int bi[8];
#pragma unroll
    for (int s = 0; s < 8; s++) { bv[s] = -3.4e38f; v2[s] = -3.4e38f; bi[s] = 0; }

    const unsigned aRowOff = (unsigned)(wr * 64 + (lane & 15)) * STRIDE_A
                             + ((lane >> 4) * 16);
    const unsigned bRowOff = (unsigned)(wc * 32 + ((lane >> 4) * 8) + (lane & 7)) * STRIDE_B
                             + (((lane >> 3) & 1) * 16);

    for (int ch = 0; ch < 8; ch++) {
        CP_WAIT1();
        __syncthreads();                       // chunk ch resident

        float d[4][4][4];
#pragma unroll
        for (int mt = 0; mt < 4; mt++)
#pragma unroll
            for (int nt = 0; nt < 4; nt++)
#pragma unroll
                for (int e = 0; e < 4; e++) d[mt][nt][e] = 0.f;

        const unsigned Abase = sb + S_A + aRowOff;
        const unsigned Bbase = sb + ((ch & 1) ? S_B1 : S_B0) + bRowOff;

#pragma unroll
        for (int kk = 0; kk < 8; kk++) {
            unsigned ah[4][4], al[4][4];
#pragma unroll
            for (int mt = 0; mt < 4; mt++) {
                LDSM_X4(ah[mt], Abase + mt * (16 * STRIDE_A) + kk * 32);
                LDSM_X4(al[mt], Abase + mt * (16 * STRIDE_A) + 256 + kk * 32);
            }
            unsigned bh[2][4];
#pragma unroll
            for (int j = 0; j < 2; j++)
                LDSM_X4(bh[j], Bbase + j * (16 * STRIDE_B) + kk * 32);
#pragma unroll
            for (int mt = 0; mt < 4; mt++)
#pragma unroll
                for (int nt = 0; nt < 4; nt++) {
                    unsigned b0 = bh[nt >> 1][(nt & 1) * 2];
                    unsigned b1 = bh[nt >> 1][(nt & 1) * 2 + 1];
                    MMA16816(d[mt][nt], ah[mt], b0, b1);   // xh·eh
                    MMA16816(d[mt][nt], al[mt], b0, b1);   // xl·eh
                }
        }

        // ---- fold -0.5||e||^2, running top-2 ----
        const int cb = ch * 128 + wc * 32 + (lane & 3) * 2;
#pragma unroll
        for (int mt = 0; mt < 4; mt++)
#pragma unroll
            for (int h = 0; h < 2; h++) {
                const int s = mt * 2 + h;
#pragma unroll
                for (int nt = 0; nt < 4; nt++)
#pragma unroll
                    for (int e = 0; e < 2; e++) {
                        int code = cb + nt * 8 + e;
                        float v = d[mt][nt][h * 2 + e] - hnS[code];
                        if (v > bv[s]) { v2[s] = bv[s]; bv[s] = v; bi[s] = code; }
                        else if (v > v2[s]) v2[s] = v;
                    }
            }

        __syncthreads();
        if (ch + 2 < 8) { load_B_async(sb, ch + 2, (ch & 1) ? S_B1 : S_B0, tid); CP_COMMIT(); }
    }

    // ---- reduce across 4 lanes sharing each row ----
#pragma unroll
    for (int s = 0; s < 8; s++) {
#pragma unroll
        for (int off = 1; off <= 2; off <<= 1) {
            float ov = __shfl_xor_sync(0xffffffffu, bv[s], off);
            float o2 = __shfl_xor_sync(0xffffffffu, v2[s], off);
            int   oi = __shfl_xor_sync(0xffffffffu, bi[s], off);
            float mn = fminf(bv[s], ov);
            v2[s] = fmaxf(fmaxf(v2[s], o2), mn);
            if (ov > bv[s] || (ov == bv[s] && oi < bi[s])) { bv[s] = ov; bi[s] = oi; }
        }
    }
    if ((lane & 3) == 0) {
#pragma unroll
        for (int s = 0; s < 8; s++) {
            int mt = s >> 1, h = s & 1;
            int r = wr * 64 + mt * 16 + h * 8 + (lane >> 2);
            ((float*)(smem + S_BV))[wc * 128 + r] = bv[s];
            ((float*)(smem + S_V2))[wc * 128 + r] = v2[s];
            ((int*)(smem + S_BI))[wc * 128 + r]   = bi[s];
        }
    }
    __syncthreads();

    // ---- merge strips, write ind, flag small margins (row-adaptive) ----
    if (tid < 128) {
        float B = -3.4e38f, S2 = -3.4e38f; int I = 0;
#pragma unroll
        for (int w = 0; w < 4; w++) {
            float ov = ((const float*)(smem + S_BV))[w * 128 + tid];
            float o2 = ((const float*)(smem + S_V2))[w * 128 + tid];
            int   oi = ((const int*)(smem + S_BI))[w * 128 + tid];
            float mn = fminf(B, ov);
            S2 = fmaxf(fmaxf(S2, o2), mn);
            if (ov > B || (ov == B && oi < I)) { B = ov; I = oi; }
        }
        int row = rowBase + tid;
        if (out_ind) out_ind[row] = (float)I;
        float eps = 0.012f * sqrtf(xnS[tid]);
        if (B - S2 < eps) {
            int s = atomicAdd(&g_rcnt, 1);
            if (s < NROWS) g_rrows[s] = row;
        }
        ((int*)(smem + S_IND))[tid] = I;
    }
    __syncthreads();

    // ---- cooperative gather of quantize rows ----
    if (out_q) {
        const int* inds = (const int*)(smem + S_IND);
        for (int i = tid; i < 128 * 32; i += 256) {
            int r = i >> 5, c4 = i & 31;
            float4 v = ((const float4*)(embed + (size_t)inds[r] * 128))[c4];
            ((float4*)(out_q + (size_t)(rowBase + r) * 128))[c4] = v;
        }
    }
}

// ---------------------------------------------------------------------------
// BATCHED rescue: 16 flagged rows per block. Embed streamed through smem in
// 64-code chunks shared by all rows -> 32KB L2 traffic per row (16x less).
// Thread (row = tid&15, cg = tid>>4) scores 4 codes per chunk for its row.
// ---------------------------------------------------------------------------
#define R_ROWS 16
__global__ __launch_bounds__(256, 1)
void rescue_kernel(const float* __restrict__ x,
                   const float* __restrict__ embed,
                   float* __restrict__ out_ind,
                   float* __restrict__ out_q) {
    __shared__ float xs[R_ROWS * 128];     // 8 KB
    __shared__ float es[64 * 128];         // 32 KB
    __shared__ float hns[64];
    __shared__ int   rowIdx[R_ROWS];
    __shared__ float rbv[R_ROWS][16];
    __shared__ int   rbi[R_ROWS][16];
    const int tid = threadIdx.x;
    const int myRow = tid & 15;
    const int cg    = tid >> 4;            // 0..15
    const int cnt = g_rcnt < NROWS ? g_rcnt : NROWS;

    for (int base = blockIdx.x * R_ROWS; base < cnt; base += gridDim.x * R_ROWS) {
        const int nr = (cnt - base < R_ROWS) ? (cnt - base) : R_ROWS;
        if (tid < R_ROWS)
            rowIdx[tid] = g_rrows[base + ((tid < nr) ? tid : 0)];
        __syncthreads();
        for (int i = tid; i < nr * 32; i += 256) {
            int r = i >> 5, c4 = i & 31;
            ((float4*)xs)[r * 32 + c4] =
                ((const float4*)(x + (size_t)rowIdx[r] * 128))[c4];
        }

        float bv = -3.4e38f;
        int   bi = 0;
        for (int ch = 0; ch < 16; ch++) {
            __syncthreads();
            for (int i = tid; i < 64 * 32; i += 256)
                ((float4*)es)[i] = ((const float4*)(embed + (size_t)ch * 64 * 128))[i];
            if (tid < 64) hns[tid] = g_hn[ch * 64 + tid];
            __syncthreads();
            if (myRow < nr) {
                const float4* x4 = (const float4*)(xs + myRow * 128);
#pragma unroll
                for (int j = 0; j < 4; j++) {
                    int lc = cg * 4 + j;
                    const float4* e4 = (const float4*)(es + lc * 128);
                    float s0 = 0.f, s1 = 0.f, s2 = 0.f, s3 = 0.f;
#pragma unroll
                    for (int i = 0; i < 8; i++) {
                        float4 xa = x4[i * 4 + 0], ea = e4[i * 4 + 0];
                        float4 xb = x4[i * 4 + 1], eb = e4[i * 4 + 1];
                        float4 xc = x4[i * 4 + 2], ec = e4[i * 4 + 2];
                        float4 xd = x4[i * 4 + 3], ed = e4[i * 4 + 3];
                        s0 = fmaf(xa.x, ea.x, fmaf(xa.y, ea.y, fmaf(xa.z, ea.z, fmaf(xa.w, ea.w, s0))));
                        s1 = fmaf(xb.x, eb.x, fmaf(xb.y, eb.y, fmaf(xb.z, eb.z, fmaf(xb.w, eb.w, s1))));
                        s2 = fmaf(xc.x, ec.x, fmaf(xc.y, ec.y, fmaf(xc.z, ec.z, fmaf(xc.w, ec.w, s2))));
                        s3 = fmaf(xd.x, ed.x, fmaf(xd.y, ed.y, fmaf(xd.z, ed.z, fmaf(xd.w, ed.w, s3))));
                    }
                    float s = (s0 + s1) + (s2 + s3) - hns[lc];
                    int code = ch * 64 + lc;
                    if (s > bv) { bv = s; bi = code; }   // codes ascending -> first-max
                }
            }
        }
        rbv[myRow][cg] = bv;
        rbi[myRow][cg] = bi;
        __syncthreads();

        if (tid < nr) {
            float B = rbv[tid][0]; int I = rbi[tid][0];
#pragma unroll
            for (int g = 1; g < 16; g++) {
                float ov = rbv[tid][g]; int oi = rbi[tid][g];
                if (ov > B || (ov == B && oi < I)) { B = ov; I = oi; }
            }
            if (out_ind) out_ind[rowIdx[tid]] = (float)I;
            rbi[tid][0] = I;
        }
        __syncthreads();
        if (out_q) {
            for (int i = tid; i < nr * 32; i += 256) {
                int r = i >> 5, c4 = i & 31;
                ((float4*)(out_q + (size_t)rowIdx[r] * 128))[c4] =
                    ((const float4*)(embed + (size_t)rbi[r][0] * 128))[c4];
            }
        }
        __syncthreads();
    }
}

// ---------------------------------------------------------------------------
extern "C" void kernel_launch(void* const* d_in, const int* in_sizes, int n_in,
                              void* d_out, int out_size) {
    const float* x     = (const float*)d_in[0];
    const float* embed = (const float*)d_in[1];
    const int N = in_sizes[0] / 128;   // 131072

    float* out     = (float*)d_out;
    float* out_ind = out;              // layout: [ind (N)][quantize (N*128)]
    float* out_q   = out + N;
    long long os = (long long)out_size;
    if (os == (long long)N * 128) { out_ind = nullptr; out_q = out; }
    else if (os == (long long)N)  { out_q = nullptr; }

    prep_e<<<KCODES / 8, 256>>>(embed);

    cudaFuncSetAttribute(vq_main, cudaFuncAttributeMaxDynamicSharedMemorySize,
                         S_TOTAL);
    vq_main<<<N / 128, 256, S_TOTAL>>>(x, embed, out_ind, out_q);

    rescue_kernel<<<512, 256>>>(x, embed, out_ind, out_q);
}